// round 3
// baseline (speedup 1.0000x reference)
#include <cuda_runtime.h>
#include <cstdint>

// Problem constants
#define TOKENS 16384          // B*S = 4*4096
#define K_DIM 4096            // D_IN
#define O_DIM 4096            // D_OUT
#define R_DIM 16

// GEMM1 tiling
#define KSPLIT 8
#define TOKA 256              // tokens per block (1 per thread)
#define KT 16                 // k per smem tile
#define KPB (K_DIM / KSPLIT)  // 512 k per block
#define NTILE (KPB / KT)      // 32 tiles

// GEMM2 tiling
#define TOKB 32
#define OTILE 512

// Scratch (no cudaMalloc allowed)
__device__ float g_part[KSPLIT][TOKENS][R_DIM];   // 8 MB partial new_x
__device__ float g_sdup[TOKENS][2 * R_DIM];       // 2 MB duplicated+scaled s

typedef unsigned long long u64;

__device__ __forceinline__ u64 pack2(float lo, float hi) {
    u64 r;
    asm("mov.b64 %0, {%1, %2};" : "=l"(r) : "f"(lo), "f"(hi));
    return r;
}
__device__ __forceinline__ void fma2(u64& d, u64 a, u64 b) {
    asm("fma.rn.f32x2 %0, %1, %2, %0;" : "+l"(d) : "l"(a), "l"(b));
}
__device__ __forceinline__ u64 add2(u64 a, u64 b) {
    u64 r;
    asm("add.rn.f32x2 %0, %1, %2;" : "=l"(r) : "l"(a), "l"(b));
    return r;
}
__device__ __forceinline__ float2 unp2(u64 v) {
    float2 f;
    asm("mov.b64 {%0, %1}, %2;" : "=f"(f.x), "=f"(f.y) : "l"(v));
    return f;
}

// ---------------------------------------------------------------------------
// Kernel A: split-K partial of new_x = x @ W_a
// grid (64, 8), block 256. Thread owns one token; K slice = 512.
// ---------------------------------------------------------------------------
__global__ void __launch_bounds__(256, 2) k_gemm1(
    const float* __restrict__ x, const float* __restrict__ Wa)
{
    __shared__ float xs[2][TOKA * 17];        // pad 17 -> conflict-free LDS
    __shared__ float ws[2][KT * R_DIM];

    const int tid = threadIdx.x;
    const int tokBase = blockIdx.x * TOKA;
    const int kBase = blockIdx.y * KPB;

    u64 acc[8];
    #pragma unroll
    for (int i = 0; i < 8; i++) acc[i] = pack2(0.f, 0.f);

    float4 xr[4];
    float4 wr;

    // --- prologue: load + store tile 0 ---
    #pragma unroll
    for (int i = 0; i < 4; i++) {
        int idx = tid + i * 256;
        int tok = idx >> 2, k4 = idx & 3;
        xr[i] = *reinterpret_cast<const float4*>(
            x + (size_t)(tokBase + tok) * K_DIM + kBase + k4 * 4);
    }
    if (tid < 64)
        wr = *reinterpret_cast<const float4*>(Wa + kBase * R_DIM + tid * 4);
    #pragma unroll
    for (int i = 0; i < 4; i++) {
        int idx = tid + i * 256;
        int tok = idx >> 2, k4 = idx & 3;
        float* d = &xs[0][tok * 17 + k4 * 4];
        d[0] = xr[i].x; d[1] = xr[i].y; d[2] = xr[i].z; d[3] = xr[i].w;
    }
    if (tid < 64)
        *reinterpret_cast<float4*>(&ws[0][tid * 4]) = wr;
    __syncthreads();

    #pragma unroll 2
    for (int t = 0; t < NTILE; t++) {
        const int cur = t & 1;
        // prefetch next tile into registers (overlaps with compute)
        if (t + 1 < NTILE) {
            const int kb = kBase + (t + 1) * KT;
            #pragma unroll
            for (int i = 0; i < 4; i++) {
                int idx = tid + i * 256;
                int tok = idx >> 2, k4 = idx & 3;
                xr[i] = *reinterpret_cast<const float4*>(
                    x + (size_t)(tokBase + tok) * K_DIM + kb + k4 * 4);
            }
            if (tid < 64)
                wr = *reinterpret_cast<const float4*>(Wa + kb * R_DIM + tid * 4);
        }
        // compute on current buffer
        const float* xrow = &xs[cur][tid * 17];
        #pragma unroll
        for (int j = 0; j < KT; j++) {
            float xv = xrow[j];
            u64 xx = pack2(xv, xv);
            const ulonglong2* w =
                reinterpret_cast<const ulonglong2*>(&ws[cur][j * R_DIM]);
            #pragma unroll
            for (int q = 0; q < 4; q++) {
                ulonglong2 p = w[q];     // LDS.128: (Wa[k][4q..4q+1], [4q+2..4q+3])
                fma2(acc[2 * q + 0], xx, p.x);
                fma2(acc[2 * q + 1], xx, p.y);
            }
        }
        // store next tile to the other buffer
        if (t + 1 < NTILE) {
            const int nxt = (t + 1) & 1;
            #pragma unroll
            for (int i = 0; i < 4; i++) {
                int idx = tid + i * 256;
                int tok = idx >> 2, k4 = idx & 3;
                float* d = &xs[nxt][tok * 17 + k4 * 4];
                d[0] = xr[i].x; d[1] = xr[i].y; d[2] = xr[i].z; d[3] = xr[i].w;
            }
            if (tid < 64)
                *reinterpret_cast<float4*>(&ws[nxt][tid * 4]) = wr;
        }
        __syncthreads();
    }

    // write 16 partial sums
    float2 f[8];
    #pragma unroll
    for (int i = 0; i < 8; i++) f[i] = unp2(acc[i]);
    float* dst = &g_part[blockIdx.y][tokBase + tid][0];
    #pragma unroll
    for (int q = 0; q < 4; q++) {
        float4 v = make_float4(f[2 * q].x, f[2 * q].y, f[2 * q + 1].x, f[2 * q + 1].y);
        reinterpret_cast<float4*>(dst)[q] = v;
    }
}

// ---------------------------------------------------------------------------
// Kernel A2: reduce split-K partials + recurrent mix + min-max norm + leaky,
// store s = ALPHA*(new_x + act) duplicated per element for packed f32x2 GEMM2.
// grid 64, block 256 (thread per token).
// ---------------------------------------------------------------------------
__global__ void __launch_bounds__(256) k_epilogue(
    const float* __restrict__ h, const float* __restrict__ Wc,
    const float* __restrict__ Wd)
{
    __shared__ float wc[R_DIM * R_DIM], wd[R_DIM * R_DIM];
    const int tid = threadIdx.x;
    wc[tid] = Wc[tid];
    wd[tid] = Wd[tid];
    __syncthreads();

    const int tok = blockIdx.x * 256 + tid;

    float nx[16];
    #pragma unroll
    for (int q = 0; q < 4; q++) {
        float4 v = *reinterpret_cast<const float4*>(&g_part[0][tok][q * 4]);
        nx[q * 4 + 0] = v.x; nx[q * 4 + 1] = v.y;
        nx[q * 4 + 2] = v.z; nx[q * 4 + 3] = v.w;
    }
    #pragma unroll
    for (int p = 1; p < KSPLIT; p++) {
        #pragma unroll
        for (int q = 0; q < 4; q++) {
            float4 v = *reinterpret_cast<const float4*>(&g_part[p][tok][q * 4]);
            nx[q * 4 + 0] += v.x; nx[q * 4 + 1] += v.y;
            nx[q * 4 + 2] += v.z; nx[q * 4 + 3] += v.w;
        }
    }

    float hv[16];
    #pragma unroll
    for (int q = 0; q < 4; q++) {
        float4 v = *reinterpret_cast<const float4*>(h + (size_t)tok * R_DIM + q * 4);
        hv[q * 4 + 0] = v.x; hv[q * 4 + 1] = v.y;
        hv[q * 4 + 2] = v.z; hv[q * 4 + 3] = v.w;
    }

    // h_t1 = h + h @ Wc + new_x @ Wd
    float ht[16];
    #pragma unroll
    for (int r = 0; r < 16; r++) ht[r] = hv[r];
    #pragma unroll
    for (int j = 0; j < 16; j++) {
        float a = hv[j], b = nx[j];
        #pragma unroll
        for (int q = 0; q < 4; q++) {
            float4 c = *reinterpret_cast<const float4*>(&wc[j * 16 + q * 4]);
            float4 d = *reinterpret_cast<const float4*>(&wd[j * 16 + q * 4]);
            ht[q * 4 + 0] = fmaf(a, c.x, fmaf(b, d.x, ht[q * 4 + 0]));
            ht[q * 4 + 1] = fmaf(a, c.y, fmaf(b, d.y, ht[q * 4 + 1]));
            ht[q * 4 + 2] = fmaf(a, c.z, fmaf(b, d.z, ht[q * 4 + 2]));
            ht[q * 4 + 3] = fmaf(a, c.w, fmaf(b, d.w, ht[q * 4 + 3]));
        }
    }

    float mn = ht[0], mx = ht[0];
    #pragma unroll
    for (int r = 1; r < 16; r++) {
        mn = fminf(mn, ht[r]);
        mx = fmaxf(mx, ht[r]);
    }
    const float inv = 1.0f / (mx - mn + 1e-8f);

    #pragma unroll
    for (int q = 0; q < 8; q++) {
        float s2[2];
        #pragma unroll
        for (int u = 0; u < 2; u++) {
            int r = 2 * q + u;
            float hn = (ht[r] - mn) * inv;
            float act = (hn < 0.f) ? 0.01f * hn : hn;
            s2[u] = 32.0f * (nx[r] + act);     // ALPHA folded here
        }
        float4 v = make_float4(s2[0], s2[0], s2[1], s2[1]);  // duplicated pairs
        *reinterpret_cast<float4*>(&g_sdup[tok][q * 4]) = v;
    }
}

// ---------------------------------------------------------------------------
// Kernel B: y = s_dup @ W_b  (packed f32x2; W_b pairs held in registers)
// grid 512, block 256; block does 32 tokens x 4096 outputs.
// ---------------------------------------------------------------------------
__global__ void __launch_bounds__(256) k_gemm2(
    const float* __restrict__ Wb, float* __restrict__ y)
{
    __shared__ float sd[TOKB * 32];    // 4 KB duplicated s for this token strip
    const int tid = threadIdx.x;
    const int tokBase = blockIdx.x * TOKB;

    *reinterpret_cast<float4*>(&sd[tid * 4]) =
        *reinterpret_cast<const float4*>(&g_sdup[tokBase][0] + tid * 4);
    __syncthreads();

    #pragma unroll 1
    for (int ot = 0; ot < O_DIM / OTILE; ot++) {
        const int o0 = ot * OTILE + tid * 2;
        u64 wb[16];
        #pragma unroll
        for (int r = 0; r < 16; r++)
            wb[r] = *reinterpret_cast<const u64*>(Wb + (size_t)r * O_DIM + o0);

        #pragma unroll 4
        for (int t = 0; t < TOKB; t++) {
            const ulonglong2* sp =
                reinterpret_cast<const ulonglong2*>(&sd[t * 32]);
            u64 a0 = pack2(0.f, 0.f), a1 = pack2(0.f, 0.f);
            #pragma unroll
            for (int q = 0; q < 8; q += 2) {
                ulonglong2 p0 = sp[q], p1 = sp[q + 1];   // (s[r],s[r]) pairs
                fma2(a0, p0.x, wb[2 * q + 0]);
                fma2(a1, p0.y, wb[2 * q + 1]);
                fma2(a0, p1.x, wb[2 * q + 2]);
                fma2(a1, p1.y, wb[2 * q + 3]);
            }
            *reinterpret_cast<u64*>(
                y + (size_t)(tokBase + t) * O_DIM + o0) = add2(a0, a1);
        }
    }
}

// ---------------------------------------------------------------------------
extern "C" void kernel_launch(void* const* d_in, const int* in_sizes, int n_in,
                              void* d_out, int out_size)
{
    const float* x  = (const float*)d_in[0];
    const float* h  = (const float*)d_in[1];
    const float* Wa = (const float*)d_in[2];
    const float* Wb = (const float*)d_in[3];
    const float* Wc = (const float*)d_in[4];
    const float* Wd = (const float*)d_in[5];
    float* y = (float*)d_out;

    dim3 gA(TOKENS / TOKA, KSPLIT);           // (64, 8)
    k_gemm1<<<gA, 256>>>(x, Wa);
    k_epilogue<<<TOKENS / 256, 256>>>(h, Wc, Wd);   // 64 blocks
    k_gemm2<<<TOKENS / TOKB, 256>>>(Wb, y);         // 512 blocks
}

// round 7
// speedup vs baseline: 1.4364x; 1.4364x over previous
#include <cuda_runtime.h>
#include <cstdint>

// Problem constants
#define TOKENS 16384          // B*S
#define K_DIM 4096
#define O_DIM 4096
#define R_DIM 16

// GEMM1 tiling
#define KSPLIT 8
#define TOKA 128              // tokens per block
#define KTA 16                // k per tile
#define KPB (K_DIM / KSPLIT)  // 512
#define NTA (KPB / KTA)       // 32 tiles

// GEMM2 tiling
#define TOKB 32

// Scratch (no cudaMalloc allowed)
__device__ float g_wat[R_DIM * K_DIM];            // 256 KB: Wa transposed [r][k]
__device__ float g_part[KSPLIT][TOKENS][R_DIM];   // 8 MB split-K partials
__device__ float g_sdup[TOKENS][2 * R_DIM];       // 2 MB duplicated+scaled s

typedef unsigned long long u64;

__device__ __forceinline__ u64 pack2(float lo, float hi) {
    u64 r;
    asm("mov.b64 %0, {%1, %2};" : "=l"(r) : "f"(lo), "f"(hi));
    return r;
}
__device__ __forceinline__ void fma2(u64& d, u64 a, u64 b) {
    asm("fma.rn.f32x2 %0, %1, %2, %0;" : "+l"(d) : "l"(a), "l"(b));
}
__device__ __forceinline__ float2 unp2(u64 v) {
    float2 f;
    asm("mov.b64 {%0, %1}, %2;" : "=f"(f.x), "=f"(f.y) : "l"(v));
    return f;
}
__device__ __forceinline__ void cp16(void* dst_smem, const void* src) {
    unsigned d = (unsigned)__cvta_generic_to_shared(dst_smem);
    asm volatile("cp.async.cg.shared.global [%0], [%1], 16;" :: "r"(d), "l"(src));
}
__device__ __forceinline__ void cp_commit() {
    asm volatile("cp.async.commit_group;");
}
template <int N>
__device__ __forceinline__ void cp_wait() {
    asm volatile("cp.async.wait_group %0;" :: "n"(N));
}

// ---------------------------------------------------------------------------
// Kernel T: transpose W_a [k][r] -> g_wat [r][k]  (256 KB, runs once per call)
// ---------------------------------------------------------------------------
__global__ void k_transpose(const float* __restrict__ Wa)
{
    int oidx = blockIdx.x * 256 + threadIdx.x;     // output-coalesced
    int r = oidx >> 12;            // / 4096
    int k = oidx & 4095;
    g_wat[oidx] = Wa[k * R_DIM + r];
}

// ---------------------------------------------------------------------------
// Kernel A: split-K partial of new_x = x @ W_a
// 128 threads, 128 tokens/block. Warp = 32 tokens; lane = (tg in 0..1, r in 0..15).
// acc[g] = (sum over even k, sum over odd k) for (token, r) — both FFMA2
// operands are natural contiguous pairs (no packing MOVs).
// 2-stage cp.async pipeline.
// ---------------------------------------------------------------------------
__global__ void __launch_bounds__(128, 4) k_gemm1(
    const float* __restrict__ x)
{
    __shared__ float xs[2][TOKA * KTA];     // 2 x 8 KB
    __shared__ float wst[2][R_DIM * 20];    // transposed W tile, pad-20 rows

    const int tid = threadIdx.x;
    const int lane = tid & 31;
    const int warp = tid >> 5;
    const int tg = lane >> 4;        // 0..1 token subgroup
    const int r  = lane & 15;        // r index
    const int tokBase = blockIdx.x * TOKA;
    const int kBase = blockIdx.y * KPB;

    // cp.async chunk mapping: x chunk (ctok, cj4), 4 chunks/thread/stage
    const int cj4 = tid & 3;
    const int ctok = tid >> 2;       // 0..31 (+i*32)
    const int wr_ = tid >> 2;        // ws chunk row (tid<64)
    const int wq_ = tid & 3;

    u64 acc[16];
    #pragma unroll
    for (int i = 0; i < 16; i++) acc[i] = pack2(0.f, 0.f);

    // prologue: tile 0 into stage 0
    {
        const float* s0 = x + (size_t)(tokBase + ctok) * K_DIM + kBase + cj4 * 4;
        float* d0 = &xs[0][ctok * KTA + cj4 * 4];
        #pragma unroll
        for (int i = 0; i < 4; i++)
            cp16(d0 + i * 32 * KTA, s0 + (size_t)i * 32 * K_DIM);
        if (tid < 64)
            cp16(&wst[0][wr_ * 20 + wq_ * 4],
                 g_wat + (size_t)wr_ * K_DIM + kBase + wq_ * 4);
        cp_commit();
    }

    for (int t = 0; t < NTA; t++) {
        __syncthreads();                     // next-stage buffer is free
        if (t + 1 < NTA) {
            const int st1 = (t + 1) & 1;
            const int kb1 = kBase + (t + 1) * KTA;
            const float* s0 = x + (size_t)(tokBase + ctok) * K_DIM + kb1 + cj4 * 4;
            float* d0 = &xs[st1][ctok * KTA + cj4 * 4];
            #pragma unroll
            for (int i = 0; i < 4; i++)
                cp16(d0 + i * 32 * KTA, s0 + (size_t)i * 32 * K_DIM);
            if (tid < 64)
                cp16(&wst[st1][wr_ * 20 + wq_ * 4],
                     g_wat + (size_t)wr_ * K_DIM + kb1 + wq_ * 4);
            cp_commit();
            cp_wait<1>();
        } else {
            cp_wait<0>();
        }
        __syncthreads();                     // tile t visible to all

        const int st = t & 1;
        ulonglong2 wr[4];
        {
            const ulonglong2* wrow = (const ulonglong2*)&wst[st][r * 20];
            #pragma unroll
            for (int q = 0; q < 4; q++) wr[q] = wrow[q];
        }
        #pragma unroll
        for (int g = 0; g < 16; g++) {
            const ulonglong2* xrow =
                (const ulonglong2*)&xs[st][(warp * 32 + g * 2 + tg) * KTA];
            #pragma unroll
            for (int q = 0; q < 4; q++) {
                ulonglong2 xv = xrow[q];     // (x[4q],x[4q+1]),(x[4q+2],x[4q+3])
                fma2(acc[g], xv.x, wr[q].x);
                fma2(acc[g], xv.y, wr[q].y);
            }
        }
    }

    // finalize: even+odd halves, scalar store (warp writes 128B/row-pair)
    #pragma unroll
    for (int g = 0; g < 16; g++) {
        int tok = tokBase + warp * 32 + g * 2 + tg;
        float2 v = unp2(acc[g]);
        g_part[blockIdx.y][tok][r] = v.x + v.y;
    }
}

// ---------------------------------------------------------------------------
// Kernel A2: reduce split-K partials + recurrent mix + min-max norm + leaky.
// Stores s = ALPHA*(new_x + act) duplicated per element for packed GEMM2.
// ---------------------------------------------------------------------------
__global__ void __launch_bounds__(256) k_epilogue(
    const float* __restrict__ h, const float* __restrict__ Wc,
    const float* __restrict__ Wd)
{
    __shared__ float wc[R_DIM * R_DIM], wd[R_DIM * R_DIM];
    const int tid = threadIdx.x;
    wc[tid] = Wc[tid];
    wd[tid] = Wd[tid];
    __syncthreads();

    const int tok = blockIdx.x * 256 + tid;

    float nx[16];
    #pragma unroll
    for (int q = 0; q < 4; q++) {
        float4 v = *reinterpret_cast<const float4*>(&g_part[0][tok][q * 4]);
        nx[q * 4 + 0] = v.x; nx[q * 4 + 1] = v.y;
        nx[q * 4 + 2] = v.z; nx[q * 4 + 3] = v.w;
    }
    #pragma unroll
    for (int p = 1; p < KSPLIT; p++) {
        #pragma unroll
        for (int q = 0; q < 4; q++) {
            float4 v = *reinterpret_cast<const float4*>(&g_part[p][tok][q * 4]);
            nx[q * 4 + 0] += v.x; nx[q * 4 + 1] += v.y;
            nx[q * 4 + 2] += v.z; nx[q * 4 + 3] += v.w;
        }
    }

    float hv[16];
    #pragma unroll
    for (int q = 0; q < 4; q++) {
        float4 v = *reinterpret_cast<const float4*>(h + (size_t)tok * R_DIM + q * 4);
        hv[q * 4 + 0] = v.x; hv[q * 4 + 1] = v.y;
        hv[q * 4 + 2] = v.z; hv[q * 4 + 3] = v.w;
    }

    float ht[16];
    #pragma unroll
    for (int rr = 0; rr < 16; rr++) ht[rr] = hv[rr];
    #pragma unroll
    for (int j = 0; j < 16; j++) {
        float a = hv[j], b = nx[j];
        #pragma unroll
        for (int q = 0; q < 4; q++) {
            float4 c = *reinterpret_cast<const float4*>(&wc[j * 16 + q * 4]);
            float4 d = *reinterpret_cast<const float4*>(&wd[j * 16 + q * 4]);
            ht[q * 4 + 0] = fmaf(a, c.x, fmaf(b, d.x, ht[q * 4 + 0]));
            ht[q * 4 + 1] = fmaf(a, c.y, fmaf(b, d.y, ht[q * 4 + 1]));
            ht[q * 4 + 2] = fmaf(a, c.z, fmaf(b, d.z, ht[q * 4 + 2]));
            ht[q * 4 + 3] = fmaf(a, c.w, fmaf(b, d.w, ht[q * 4 + 3]));
        }
    }

    float mn = ht[0], mx = ht[0];
    #pragma unroll
    for (int rr = 1; rr < 16; rr++) {
        mn = fminf(mn, ht[rr]);
        mx = fmaxf(mx, ht[rr]);
    }
    const float inv = 1.0f / (mx - mn + 1e-8f);

    #pragma unroll
    for (int q = 0; q < 8; q++) {
        float s2[2];
        #pragma unroll
        for (int u = 0; u < 2; u++) {
            int rr = 2 * q + u;
            float hn = (ht[rr] - mn) * inv;
            float act = (hn < 0.f) ? 0.01f * hn : hn;
            s2[u] = 32.0f * (nx[rr] + act);
        }
        float4 v = make_float4(s2[0], s2[0], s2[1], s2[1]);
        *reinterpret_cast<float4*>(&g_sdup[tok][q * 4]) = v;
    }
}

// ---------------------------------------------------------------------------
// Kernel B: y = s_dup @ W_b. 4 outputs/thread, STG.128.
// grid 512, block 256; block = 32 tokens x 4096 outputs (4 ot strips of 1024).
// ---------------------------------------------------------------------------
__global__ void __launch_bounds__(256) k_gemm2(
    const float* __restrict__ Wb, float* __restrict__ y)
{
    __shared__ float sd[TOKB * 32];    // 4 KB duplicated s
    const int tid = threadIdx.x;
    const int tokBase = blockIdx.x * TOKB;

    *reinterpret_cast<float4*>(&sd[tid * 4]) =
        *reinterpret_cast<const float4*>(&g_sdup[tokBase][0] + tid * 4);
    __syncthreads();

    #pragma unroll 1
    for (int ot = 0; ot < 4; ot++) {
        const int o0 = ot * 1024 + tid * 4;
        ulonglong2 wb[16];
        #pragma unroll
        for (int rr = 0; rr < 16; rr++)
            wb[rr] = *reinterpret_cast<const ulonglong2*>(
                Wb + (size_t)rr * O_DIM + o0);

        #pragma unroll 2
        for (int t = 0; t < TOKB; t++) {
            const ulonglong2* sp =
                reinterpret_cast<const ulonglong2*>(&sd[t * 32]);
            u64 a0 = pack2(0.f, 0.f), a1 = pack2(0.f, 0.f);
            #pragma unroll
            for (int q = 0; q < 8; q++) {
                ulonglong2 p = sp[q];     // (s2q,s2q),(s2q+1,s2q+1)
                fma2(a0, p.x, wb[2 * q + 0].x);
                fma2(a1, p.x, wb[2 * q + 0].y);
                fma2(a0, p.y, wb[2 * q + 1].x);
                fma2(a1, p.y, wb[2 * q + 1].y);
            }
            ulonglong2 out;
            out.x = a0; out.y = a1;
            *reinterpret_cast<ulonglong2*>(
                y + (size_t)(tokBase + t) * O_DIM + o0) = out;
        }
    }
}

// ---------------------------------------------------------------------------
extern "C" void kernel_launch(void* const* d_in, const int* in_sizes, int n_in,
                              void* d_out, int out_size)
{
    const float* x  = (const float*)d_in[0];
    const float* h  = (const float*)d_in[1];
    const float* Wa = (const float*)d_in[2];
    const float* Wb = (const float*)d_in[3];
    const float* Wc = (const float*)d_in[4];
    const float* Wd = (const float*)d_in[5];
    float* y = (float*)d_out;

    k_transpose<<<(R_DIM * K_DIM) / 256, 256>>>(Wa);
    dim3 gA(TOKENS / TOKA, KSPLIT);               // (128, 8)
    k_gemm1<<<gA, 128>>>(x);
    k_epilogue<<<TOKENS / 256, 256>>>(h, Wc, Wd); // 64 blocks
    k_gemm2<<<TOKENS / TOKB, 256>>>(Wb, y);       // 512 blocks
}